// round 6
// baseline (speedup 1.0000x reference)
#include <cuda_runtime.h>
#include <cuda_bf16.h>
#include <cstdint>

// ---------------- problem constants ----------------
#define N_AG 2048           // B*Amax
#define T_K 16
#define D_F 10
#define E_F 128
#define H_F 512
#define M3 (E_F * D_F)      // 1280
#define ND (N_AG * D_F)     // 20480
#define NPTS 60
#define NE (N_AG * E_F)     // 262144

// ---------------- scratch ----------------
__device__ float g_M[T_K * ND];
__device__ float g_dX[NPTS * ND];
__device__ float g_z[NE];
__device__ float g_k1[NE];
__device__ float g_k2[NE];
__device__ float g_k3[NE];
__device__ float g_y3[N_AG * M3];     // layout [n][d*128+e]
__device__ float g_b3p[M3];           // permuted bias for layer 3

#define BF16A __device__ __align__(16) __nv_bfloat16
BF16A g_zh[NE],   g_zl[NE];
BF16A g_zinh[NE], g_zinl[NE];
BF16A g_y0h[N_AG * H_F], g_y0l[N_AG * H_F];
BF16A g_y1h[N_AG * H_F], g_y1l[N_AG * H_F];
BF16A g_y2h[N_AG * H_F], g_y2l[N_AG * H_F];
BF16A g_W0h[H_F * E_F], g_W0l[H_F * E_F];
BF16A g_W1h[H_F * H_F], g_W1l[H_F * H_F];
BF16A g_W2h[H_F * H_F], g_W2l[H_F * H_F];
BF16A g_W3h[M3 * H_F],  g_W3l[M3 * H_F];   // rows permuted: dst row = d*128+e

// ---------------- helpers ----------------
__device__ __forceinline__ uint32_t smem_u32(const void* p) {
    uint32_t a;
    asm("{ .reg .u64 t; cvta.to.shared.u64 t, %1; cvt.u32.u64 %0, t; }" : "=r"(a) : "l"(p));
    return a;
}
__device__ __forceinline__ void cp16(uint32_t s, const void* g) {
    asm volatile("cp.async.cg.shared.global [%0], [%1], 16;" :: "r"(s), "l"(g));
}
__device__ __forceinline__ void ldsm4(uint32_t& r0, uint32_t& r1, uint32_t& r2, uint32_t& r3,
                                      uint32_t a) {
    asm volatile("ldmatrix.sync.aligned.m8n8.x4.shared.b16 {%0,%1,%2,%3}, [%4];"
                 : "=r"(r0), "=r"(r1), "=r"(r2), "=r"(r3) : "r"(a));
}
__device__ __forceinline__ void mma16816(float& c0, float& c1, float& c2, float& c3,
                                         uint32_t a0, uint32_t a1, uint32_t a2, uint32_t a3,
                                         uint32_t b0, uint32_t b1) {
    asm volatile("mma.sync.aligned.m16n8k16.row.col.f32.bf16.bf16.f32 "
                 "{%0,%1,%2,%3},{%4,%5,%6,%7},{%8,%9},{%0,%1,%2,%3};"
                 : "+f"(c0), "+f"(c1), "+f"(c2), "+f"(c3)
                 : "r"(a0), "r"(a1), "r"(a2), "r"(a3), "r"(b0), "r"(b1));
}
__device__ __forceinline__ uint32_t pack_bf16(float lo, float hi) {
    uint32_t r;
    asm("cvt.rn.bf16x2.f32 %0, %1, %2;" : "=r"(r) : "f"(hi), "f"(lo));
    return r;
}
__device__ __forceinline__ float fast_tanh(float x) {
    x = fminf(fmaxf(x, -15.f), 15.f);
    float e = __expf(-2.f * x);
    return (1.f - e) * __frcp_rn(1.f + e);
}

// smem layout per buffer: row stride 72 halves (144 B) -> conflict-free ldmatrix
#define STRIDE 72
#define OFF_AH 0
#define OFF_AL 18432
#define OFF_BH 36864
#define OFF_BL 46080
#define BUF_B  55296
#define SMEM_BYTES (2 * BUF_B)      // 110592

// ---------------- split-bf16 HMMA GEMM (ldmatrix, BK=64) ----------------
// C = act(A(NxK) @ W(MoutxK)^T + bias). CTA 128x64, 8 warps 4(M)x2(N), warp 32x32.
// D = Ah*Bh + Ah*Bl + Al*Bh, fp32 accum.
template <int ACT>  // 0: relu + split bf16 out; 1: tanh + fp32 out
__global__ void __launch_bounds__(256) mma_gemm(
    const __nv_bfloat16* __restrict__ Ah, const __nv_bfloat16* __restrict__ Al,
    const __nv_bfloat16* __restrict__ Bh, const __nv_bfloat16* __restrict__ Bl,
    const float* __restrict__ bias,
    __nv_bfloat16* __restrict__ Ch, __nv_bfloat16* __restrict__ Cl,
    float* __restrict__ Cf, int K, int Mout)
{
    extern __shared__ char smem[];
    const uint32_t sb = smem_u32(smem);
    const int tid = threadIdx.x, wid = tid >> 5, lid = tid & 31;
    const int rowBase = blockIdx.y * 128;
    const int colBase = blockIdx.x * 64;
    const int warpM = (wid & 3) * 32;
    const int warpN = (wid >> 2) * 32;
    const int grp = lid >> 2, q = lid & 3;

    // cp.async thread mapping (BK=64 halves per row)
    const int ar  = tid >> 1;              // A row 0..127
    const int acb = (tid & 1) * 32;        // half offset within row
    const int br2 = tid >> 2;              // B row 0..63
    const int bcb = (tid & 3) * 16;

    const __nv_bfloat16* gAh = Ah + (size_t)(rowBase + ar) * K + acb;
    const __nv_bfloat16* gAl = Al + (size_t)(rowBase + ar) * K + acb;
    const __nv_bfloat16* gBh = Bh + (size_t)(colBase + br2) * K + bcb;
    const __nv_bfloat16* gBl = Bl + (size_t)(colBase + br2) * K + bcb;

    const uint32_t sAh = sb + OFF_AH + (ar * STRIDE + acb) * 2;
    const uint32_t sAl = sb + OFF_AL + (ar * STRIDE + acb) * 2;
    const uint32_t sBh = sb + OFF_BH + (br2 * STRIDE + bcb) * 2;
    const uint32_t sBl = sb + OFF_BL + (br2 * STRIDE + bcb) * 2;

    // ldmatrix lane addressing
    const int sel  = lid >> 3;
    const int lrow = (sel & 1) * 8 + (lid & 7);
    const int lcol = (sel >> 1) * 8;
    const uint32_t aoff0 = ((warpM + lrow) * STRIDE + lcol) * 2;
    const uint32_t aoff1 = ((warpM + 16 + lrow) * STRIDE + lcol) * 2;
    const uint32_t boff0 = ((warpN + lrow) * STRIDE + lcol) * 2;
    const uint32_t boff1 = ((warpN + 16 + lrow) * STRIDE + lcol) * 2;

    float c[2][4][4];
#pragma unroll
    for (int mi = 0; mi < 2; mi++)
#pragma unroll
        for (int ni = 0; ni < 4; ni++)
#pragma unroll
            for (int r = 0; r < 4; r++) c[mi][ni][r] = 0.f;

    const int NK = K >> 6;

    // prologue: tile 0 -> buffer 0
#pragma unroll
    for (int j = 0; j < 4; j++) { cp16(sAh + j * 16, gAh + j * 8); cp16(sAl + j * 16, gAl + j * 8); }
#pragma unroll
    for (int j = 0; j < 2; j++) { cp16(sBh + j * 16, gBh + j * 8); cp16(sBl + j * 16, gBl + j * 8); }
    asm volatile("cp.async.commit_group;");

    for (int kt = 0; kt < NK; kt++) {
        if (kt + 1 < NK) {
            const int k0 = (kt + 1) << 6;
            const uint32_t bo = ((kt + 1) & 1) * BUF_B;
#pragma unroll
            for (int j = 0; j < 4; j++) {
                cp16(sAh + bo + j * 16, gAh + k0 + j * 8);
                cp16(sAl + bo + j * 16, gAl + k0 + j * 8);
            }
#pragma unroll
            for (int j = 0; j < 2; j++) {
                cp16(sBh + bo + j * 16, gBh + k0 + j * 8);
                cp16(sBl + bo + j * 16, gBl + k0 + j * 8);
            }
        }
        asm volatile("cp.async.commit_group;");
        asm volatile("cp.async.wait_group 1;");
        __syncthreads();

        const uint32_t aBase = sb + (kt & 1) * BUF_B;
#pragma unroll
        for (int kk = 0; kk < 64; kk += 16) {
            const uint32_t kb = kk * 2;
            uint32_t ah[2][4], al[2][4], bh[4][2], bl[4][2];
            ldsm4(ah[0][0], ah[0][1], ah[0][2], ah[0][3], aBase + OFF_AH + aoff0 + kb);
            ldsm4(ah[1][0], ah[1][1], ah[1][2], ah[1][3], aBase + OFF_AH + aoff1 + kb);
            ldsm4(al[0][0], al[0][1], al[0][2], al[0][3], aBase + OFF_AL + aoff0 + kb);
            ldsm4(al[1][0], al[1][1], al[1][2], al[1][3], aBase + OFF_AL + aoff1 + kb);
            ldsm4(bh[0][0], bh[1][0], bh[0][1], bh[1][1], aBase + OFF_BH + boff0 + kb);
            ldsm4(bh[2][0], bh[3][0], bh[2][1], bh[3][1], aBase + OFF_BH + boff1 + kb);
            ldsm4(bl[0][0], bl[1][0], bl[0][1], bl[1][1], aBase + OFF_BL + boff0 + kb);
            ldsm4(bl[2][0], bl[3][0], bl[2][1], bl[3][1], aBase + OFF_BL + boff1 + kb);
#pragma unroll
            for (int mi = 0; mi < 2; mi++)
#pragma unroll
                for (int ni = 0; ni < 4; ni++) {
                    float* cc = c[mi][ni];
                    mma16816(cc[0], cc[1], cc[2], cc[3],
                             ah[mi][0], ah[mi][1], ah[mi][2], ah[mi][3],
                             bh[ni][0], bh[ni][1]);
                    mma16816(cc[0], cc[1], cc[2], cc[3],
                             ah[mi][0], ah[mi][1], ah[mi][2], ah[mi][3],
                             bl[ni][0], bl[ni][1]);
                    mma16816(cc[0], cc[1], cc[2], cc[3],
                             al[mi][0], al[mi][1], al[mi][2], al[mi][3],
                             bh[ni][0], bh[ni][1]);
                }
        }
        __syncthreads();
    }

    // ---------------- epilogue ----------------
#pragma unroll
    for (int ni = 0; ni < 4; ni++) {
        const int col = colBase + warpN + ni * 8 + q * 2;
        const float bv0 = bias[col], bv1 = bias[col + 1];
#pragma unroll
        for (int mi = 0; mi < 2; mi++) {
            const int row0 = rowBase + warpM + mi * 16 + grp;
            float v00 = c[mi][ni][0] + bv0, v01 = c[mi][ni][1] + bv1;
            float v10 = c[mi][ni][2] + bv0, v11 = c[mi][ni][3] + bv1;
            if (ACT == 0) {
                v00 = fmaxf(v00, 0.f); v01 = fmaxf(v01, 0.f);
                v10 = fmaxf(v10, 0.f); v11 = fmaxf(v11, 0.f);
                uint32_t h0 = pack_bf16(v00, v01);
                uint32_t h1 = pack_bf16(v10, v11);
                float r00 = v00 - __uint_as_float(h0 << 16);
                float r01 = v01 - __uint_as_float(h0 & 0xFFFF0000u);
                float r10 = v10 - __uint_as_float(h1 << 16);
                float r11 = v11 - __uint_as_float(h1 & 0xFFFF0000u);
                *(uint32_t*)(Ch + (size_t)row0 * Mout + col) = h0;
                *(uint32_t*)(Ch + (size_t)(row0 + 8) * Mout + col) = h1;
                *(uint32_t*)(Cl + (size_t)row0 * Mout + col) = pack_bf16(r00, r01);
                *(uint32_t*)(Cl + (size_t)(row0 + 8) * Mout + col) = pack_bf16(r10, r11);
            } else {
                float2 o0 = make_float2(fast_tanh(v00), fast_tanh(v01));
                float2 o1 = make_float2(fast_tanh(v10), fast_tanh(v11));
                *(float2*)(Cf + (size_t)row0 * Mout + col) = o0;
                *(float2*)(Cf + (size_t)(row0 + 8) * Mout + col) = o1;
            }
        }
    }
}

// ---------------- weight split ----------------
__global__ void wsplit(const float* __restrict__ s, __nv_bfloat16* __restrict__ h,
                       __nv_bfloat16* __restrict__ l, int n) {
    int idx = blockIdx.x * blockDim.x + threadIdx.x;
    if (idx >= n) return;
    float v = s[idx];
    __nv_bfloat16 bh = __float2bfloat16(v);
    h[idx] = bh;
    l[idx] = __float2bfloat16(v - __bfloat162float(bh));
}

// W3 split with row permutation: src row e*10+d -> dst row d*128+e
__global__ void wsplit_w3(const float* __restrict__ s, __nv_bfloat16* __restrict__ h,
                          __nv_bfloat16* __restrict__ l) {
    int idx = blockIdx.x * blockDim.x + threadIdx.x;
    if (idx >= M3 * H_F) return;
    int r = idx >> 9, k = idx & 511;
    int e = r / D_F, d = r - e * D_F;
    size_t dst = (size_t)(d * E_F + e) * H_F + k;
    float v = s[idx];
    __nv_bfloat16 bh = __float2bfloat16(v);
    h[dst] = bh;
    l[dst] = __float2bfloat16(v - __bfloat162float(bh));
}
__global__ void b3perm(const float* __restrict__ b3) {
    int idx = blockIdx.x * blockDim.x + threadIdx.x;
    if (idx >= M3) return;
    int e = idx / D_F, d = idx - e * D_F;
    g_b3p[d * E_F + e] = b3[idx];
}

// ---------------- spline ----------------
__global__ void spline_kernel(const float* __restrict__ t, const float* __restrict__ x) {
    int col = blockIdx.x * blockDim.x + threadIdx.x;
    if (col >= ND) return;
    int n = col / D_F, d = col % D_F;
    float tv[T_K];
#pragma unroll
    for (int i = 0; i < T_K; i++) tv[i] = t[i];
    float xv[T_K];
#pragma unroll
    for (int i = 0; i < T_K; i++) xv[i] = x[(n * T_K + i) * D_F + d];
    float h[T_K - 1];
#pragma unroll
    for (int i = 0; i < T_K - 1; i++) h[i] = tv[i + 1] - tv[i];
    float cp[T_K], dp[T_K];
    cp[0] = 0.f; dp[0] = 0.f;
#pragma unroll
    for (int i = 1; i < T_K - 1; i++) {
        float rhs = 6.f * ((xv[i + 1] - xv[i]) / h[i] - (xv[i] - xv[i - 1]) / h[i - 1]);
        float m = 2.f * (h[i - 1] + h[i]) - h[i - 1] * cp[i - 1];
        float inv = 1.f / m;
        cp[i] = h[i] * inv;
        dp[i] = (rhs - h[i - 1] * dp[i - 1]) * inv;
    }
    float Mv[T_K];
    Mv[T_K - 1] = 0.f;
#pragma unroll
    for (int i = T_K - 2; i >= 0; i--) Mv[i] = dp[i] - cp[i] * Mv[i + 1];
#pragma unroll
    for (int i = 0; i < T_K; i++) g_M[i * ND + col] = Mv[i];
}

// ---------------- dX/dt ----------------
__global__ void dx_kernel(const float* __restrict__ t, const float* __restrict__ x) {
    int idx = blockIdx.x * blockDim.x + threadIdx.x;
    if (idx >= NPTS * ND) return;
    int pt = idx / ND, col = idx - pt * ND;
    int n = col / D_F, d = col - n * D_F;
    int k = pt >> 2, j = pt & 3;
    float t0 = t[k], t1 = t[k + 1];
    float hs = t1 - t0;
    float s;
    if (j == 0) s = t0;
    else if (j == 1) s = t0 + hs / 3.0f;
    else if (j == 2) s = t0 + 2.0f * hs / 3.0f;
    else s = t1;
    int cnt = 0;
#pragma unroll
    for (int i = 0; i < T_K; i++) cnt += (t[i] <= s) ? 1 : 0;
    int i = min(max(cnt - 1, 0), T_K - 2);
    float hi = t[i + 1] - t[i];
    float xi  = x[(n * T_K + i) * D_F + d];
    float xi1 = x[(n * T_K + i + 1) * D_F + d];
    float Mi  = g_M[i * ND + col];
    float Mi1 = g_M[(i + 1) * ND + col];
    float u = s - t[i];
    float b = (xi1 - xi) / hi - hi * (2.0f * Mi + Mi1) / 6.0f;
    g_dX[idx] = b + Mi * u + (Mi1 - Mi) * (u * u) / (2.0f * hi);
}

// ---------------- z0 ----------------
__global__ void z0_kernel(const float* __restrict__ x, const float* __restrict__ We,
                          const float* __restrict__ be) {
    int idx = blockIdx.x * blockDim.x + threadIdx.x;
    if (idx >= NE) return;
    int n = idx / E_F, e = idx - n * E_F;
    float acc = be[e];
#pragma unroll
    for (int d = 0; d < D_F; d++) acc += x[n * T_K * D_F + d] * We[e * D_F + d];
    g_z[idx] = acc;
    __nv_bfloat16 h = __float2bfloat16(acc);
    g_zh[idx] = h;
    g_zl[idx] = __float2bfloat16(acc - __bfloat162float(h));
}

// ---------------- fused einsum + RK combine (y3 layout [n][d*128+e]) ----------------
__global__ void vf_combine(const float* __restrict__ t, int k, int mode) {
    int idx = blockIdx.x * blockDim.x + threadIdx.x;
    if (idx >= NE) return;
    int n = idx >> 7, e = idx & 127;
    const float* y  = g_y3 + (size_t)n * M3 + e;
    const float* dx = g_dX + (size_t)(k * 4 + mode) * ND + n * D_F;
    float kv = 0.f;
#pragma unroll
    for (int d = 0; d < D_F; d++) kv += y[d * E_F] * dx[d];
    float hs = t[k + 1] - t[k];
    float z = g_z[idx];
    float zn;
    if (mode == 0)      { g_k1[idx] = kv; zn = z + hs * kv / 3.0f; }
    else if (mode == 1) { g_k2[idx] = kv; zn = z + hs * (kv - g_k1[idx] / 3.0f); }
    else if (mode == 2) { g_k3[idx] = kv; zn = z + hs * (g_k1[idx] - g_k2[idx] + kv); }
    else {
        zn = z + hs * (g_k1[idx] + 3.0f * (g_k2[idx] + g_k3[idx]) + kv) / 8.0f;
        g_z[idx] = zn;
    }
    __nv_bfloat16 h = __float2bfloat16(zn);
    __nv_bfloat16 l = __float2bfloat16(zn - __bfloat162float(h));
    if (mode == 3) { g_zh[idx] = h;   g_zl[idx] = l; }
    else           { g_zinh[idx] = h; g_zinl[idx] = l; }
}

// ---------------- output with mask ----------------
__global__ void out_kernel(const int* __restrict__ mask, float* __restrict__ out) {
    int idx = blockIdx.x * blockDim.x + threadIdx.x;
    if (idx >= NE) return;
    int n = idx / E_F;
    out[idx] = (mask[n] != 0) ? g_z[idx] : 0.0f;
}

// ---------------- launcher ----------------
extern "C" void kernel_launch(void* const* d_in, const int* in_sizes, int n_in,
                              void* d_out, int out_size) {
    const float* t  = (const float*)d_in[0];
    const float* x  = (const float*)d_in[1];
    const int*   mask = (const int*)d_in[2];
    const float* We = (const float*)d_in[3];
    const float* be = (const float*)d_in[4];
    const float* W0 = (const float*)d_in[5];
    const float* b0 = (const float*)d_in[6];
    const float* W1 = (const float*)d_in[7];
    const float* b1 = (const float*)d_in[8];
    const float* W2 = (const float*)d_in[9];
    const float* b2 = (const float*)d_in[10];
    const float* W3 = (const float*)d_in[11];
    const float* b3 = (const float*)d_in[12];

    cudaFuncSetAttribute(mma_gemm<0>, cudaFuncAttributeMaxDynamicSharedMemorySize, SMEM_BYTES);
    cudaFuncSetAttribute(mma_gemm<1>, cudaFuncAttributeMaxDynamicSharedMemorySize, SMEM_BYTES);

    __nv_bfloat16 *zh, *zl, *zinh, *zinl, *y0h, *y0l, *y1h, *y1l, *y2h, *y2l;
    __nv_bfloat16 *W0h, *W0l, *W1h, *W1l, *W2h, *W2l, *W3h, *W3l;
    float *y3, *b3p;
    cudaGetSymbolAddress((void**)&zh, g_zh);     cudaGetSymbolAddress((void**)&zl, g_zl);
    cudaGetSymbolAddress((void**)&zinh, g_zinh); cudaGetSymbolAddress((void**)&zinl, g_zinl);
    cudaGetSymbolAddress((void**)&y0h, g_y0h);   cudaGetSymbolAddress((void**)&y0l, g_y0l);
    cudaGetSymbolAddress((void**)&y1h, g_y1h);   cudaGetSymbolAddress((void**)&y1l, g_y1l);
    cudaGetSymbolAddress((void**)&y2h, g_y2h);   cudaGetSymbolAddress((void**)&y2l, g_y2l);
    cudaGetSymbolAddress((void**)&W0h, g_W0h);   cudaGetSymbolAddress((void**)&W0l, g_W0l);
    cudaGetSymbolAddress((void**)&W1h, g_W1h);   cudaGetSymbolAddress((void**)&W1l, g_W1l);
    cudaGetSymbolAddress((void**)&W2h, g_W2h);   cudaGetSymbolAddress((void**)&W2l, g_W2l);
    cudaGetSymbolAddress((void**)&W3h, g_W3h);   cudaGetSymbolAddress((void**)&W3l, g_W3l);
    cudaGetSymbolAddress((void**)&y3, g_y3);
    cudaGetSymbolAddress((void**)&b3p, g_b3p);

    wsplit<<<(H_F * E_F + 255) / 256, 256>>>(W0, W0h, W0l, H_F * E_F);
    wsplit<<<(H_F * H_F + 255) / 256, 256>>>(W1, W1h, W1l, H_F * H_F);
    wsplit<<<(H_F * H_F + 255) / 256, 256>>>(W2, W2h, W2l, H_F * H_F);
    wsplit_w3<<<(M3 * H_F + 255) / 256, 256>>>(W3, W3h, W3l);
    b3perm<<<(M3 + 255) / 256, 256>>>(b3);

    spline_kernel<<<(ND + 255) / 256, 256>>>(t, x);
    dx_kernel<<<(NPTS * ND + 255) / 256, 256>>>(t, x);
    z0_kernel<<<(NE + 255) / 256, 256>>>(x, We, be);

    dim3 gH(H_F / 64, N_AG / 128);   // (8, 16)
    dim3 g3(M3 / 64, N_AG / 128);    // (20, 16)
    int eb = (NE + 255) / 256;

    for (int k = 0; k < T_K - 1; k++) {
        for (int stage = 0; stage < 4; stage++) {
            const __nv_bfloat16* ah = (stage == 0) ? zh : zinh;
            const __nv_bfloat16* al = (stage == 0) ? zl : zinl;
            mma_gemm<0><<<gH, 256, SMEM_BYTES>>>(ah,  al,  W0h, W0l, b0, y0h, y0l, nullptr, E_F, H_F);
            mma_gemm<0><<<gH, 256, SMEM_BYTES>>>(y0h, y0l, W1h, W1l, b1, y1h, y1l, nullptr, H_F, H_F);
            mma_gemm<0><<<gH, 256, SMEM_BYTES>>>(y1h, y1l, W2h, W2l, b2, y2h, y2l, nullptr, H_F, H_F);
            mma_gemm<1><<<g3, 256, SMEM_BYTES>>>(y2h, y2l, W3h, W3l, b3p, nullptr, nullptr, y3, H_F, M3);
            vf_combine<<<eb, 256>>>(t, k, stage);
        }
    }
    out_kernel<<<eb, 256>>>(mask, (float*)d_out);
}

// round 7
// speedup vs baseline: 1.3473x; 1.3473x over previous
#include <cuda_runtime.h>
#include <cuda_fp16.h>
#include <cstdint>

// ---------------- problem constants ----------------
#define N_AG 2048
#define T_K 16
#define D_F 10
#define E_F 128
#define H_F 512
#define M3 (E_F * D_F)      // 1280
#define ND (N_AG * D_F)
#define NPTS 60
#define NE (N_AG * E_F)

// ---------------- scratch ----------------
__device__ float g_M[T_K * ND];
__device__ float g_dX[NPTS * ND];
__device__ float g_z[NE];
__device__ float g_k1[NE];
__device__ float g_k2[NE];
__device__ float g_k3[NE];
__device__ float g_y3[N_AG * M3];     // layout [n][d*128+e]
__device__ float g_b3p[M3];

#define H16A __device__ __align__(16) __half
H16A g_zh[NE],   g_zl[NE];
H16A g_zinh[NE], g_zinl[NE];
H16A g_y0h[N_AG * H_F], g_y0l[N_AG * H_F];
H16A g_y1h[N_AG * H_F], g_y1l[N_AG * H_F];
H16A g_y2h[N_AG * H_F], g_y2l[N_AG * H_F];
H16A g_W0[H_F * E_F];
H16A g_W1[H_F * H_F];
H16A g_W2[H_F * H_F];
H16A g_W3[M3 * H_F];               // rows permuted: dst row = d*128+e

// ---------------- helpers ----------------
__device__ __forceinline__ uint32_t smem_u32(const void* p) {
    uint32_t a;
    asm("{ .reg .u64 t; cvta.to.shared.u64 t, %1; cvt.u32.u64 %0, t; }" : "=r"(a) : "l"(p));
    return a;
}
__device__ __forceinline__ void cp16(uint32_t s, const void* g) {
    asm volatile("cp.async.cg.shared.global [%0], [%1], 16;" :: "r"(s), "l"(g));
}
__device__ __forceinline__ void ldsm4(uint32_t& r0, uint32_t& r1, uint32_t& r2, uint32_t& r3,
                                      uint32_t a) {
    asm volatile("ldmatrix.sync.aligned.m8n8.x4.shared.b16 {%0,%1,%2,%3}, [%4];"
                 : "=r"(r0), "=r"(r1), "=r"(r2), "=r"(r3) : "r"(a));
}
__device__ __forceinline__ void mma16816(float& c0, float& c1, float& c2, float& c3,
                                         uint32_t a0, uint32_t a1, uint32_t a2, uint32_t a3,
                                         uint32_t b0, uint32_t b1) {
    asm volatile("mma.sync.aligned.m16n8k16.row.col.f32.f16.f16.f32 "
                 "{%0,%1,%2,%3},{%4,%5,%6,%7},{%8,%9},{%0,%1,%2,%3};"
                 : "+f"(c0), "+f"(c1), "+f"(c2), "+f"(c3)
                 : "r"(a0), "r"(a1), "r"(a2), "r"(a3), "r"(b0), "r"(b1));
}
__device__ __forceinline__ uint32_t pack_h2(float lo, float hi) {
    __half2 h = __halves2half2(__float2half_rn(lo), __float2half_rn(hi));
    return *(uint32_t*)&h;
}
__device__ __forceinline__ float fast_tanh(float x) {
    x = fminf(fmaxf(x, -15.f), 15.f);
    float e = __expf(-2.f * x);
    return (1.f - e) * __frcp_rn(1.f + e);
}

// smem per buffer: STRIDE 40 halves (80 B rows). Ah 10240, Al 10240, B 5120.
#define STRIDE 40
#define OFF_AH 0
#define OFF_AL 10240
#define OFF_B  20480
#define BUF_B  25600
#define SMEM_BYTES (2 * BUF_B)      // 51200

// ---------------- fp16 2-term HMMA GEMM: C = act(A @ W^T + bias) ----------------
// CTA 128x64, BK=32, 8 warps 4(M)x2(N), warp tile 32x32, ldmatrix feeds.
// D = Ah*W + Al*W  (A split hi/lo fp16, W rounded once to fp16), fp32 accum.
template <int ACT>  // 0: relu + split fp16 out; 1: tanh + fp32 out
__global__ void __launch_bounds__(256) mma_gemm(
    const __half* __restrict__ Ah, const __half* __restrict__ Al,
    const __half* __restrict__ Bw,
    const float* __restrict__ bias,
    __half* __restrict__ Ch, __half* __restrict__ Cl,
    float* __restrict__ Cf, int K, int Mout)
{
    extern __shared__ char smem[];
    const uint32_t sb = smem_u32(smem);
    const int tid = threadIdx.x, wid = tid >> 5, lid = tid & 31;
    const int rowBase = blockIdx.y * 128;
    const int colBase = blockIdx.x * 64;
    const int warpM = (wid & 3) * 32;
    const int warpN = (wid >> 2) * 32;
    const int grp = lid >> 2, q = lid & 3;

    // cp.async mapping (BK=32)
    const int ar  = tid >> 1;            // A row 0..127
    const int acb = (tid & 1) * 16;      // half-offset
    const int br2 = tid >> 2;            // B row 0..63
    const int bcb = (tid & 3) * 8;

    const __half* gAh = Ah + (size_t)(rowBase + ar) * K + acb;
    const __half* gAl = Al + (size_t)(rowBase + ar) * K + acb;
    const __half* gB  = Bw + (size_t)(colBase + br2) * K + bcb;

    const uint32_t sAh = sb + OFF_AH + (ar * STRIDE + acb) * 2;
    const uint32_t sAl = sb + OFF_AL + (ar * STRIDE + acb) * 2;
    const uint32_t sB  = sb + OFF_B  + (br2 * STRIDE + bcb) * 2;

    // ldmatrix lane addressing
    const int sel  = lid >> 3;
    const int lrow = (sel & 1) * 8 + (lid & 7);
    const int lcol = (sel >> 1) * 8;
    const uint32_t aoff0 = ((warpM + lrow) * STRIDE + lcol) * 2;
    const uint32_t aoff1 = ((warpM + 16 + lrow) * STRIDE + lcol) * 2;
    const uint32_t boff0 = ((warpN + lrow) * STRIDE + lcol) * 2;
    const uint32_t boff1 = ((warpN + 16 + lrow) * STRIDE + lcol) * 2;

    float c[2][4][4];
#pragma unroll
    for (int mi = 0; mi < 2; mi++)
#pragma unroll
        for (int ni = 0; ni < 4; ni++)
#pragma unroll
            for (int r = 0; r < 4; r++) c[mi][ni][r] = 0.f;

    const int NK = K >> 5;

    // prologue
    cp16(sAh, gAh); cp16(sAh + 16, gAh + 8);
    cp16(sAl, gAl); cp16(sAl + 16, gAl + 8);
    cp16(sB,  gB);
    asm volatile("cp.async.commit_group;");

    for (int kt = 0; kt < NK; kt++) {
        if (kt + 1 < NK) {
            const int k0 = (kt + 1) << 5;
            const uint32_t bo = ((kt + 1) & 1) * BUF_B;
            cp16(sAh + bo, gAh + k0); cp16(sAh + bo + 16, gAh + k0 + 8);
            cp16(sAl + bo, gAl + k0); cp16(sAl + bo + 16, gAl + k0 + 8);
            cp16(sB + bo,  gB + k0);
        }
        asm volatile("cp.async.commit_group;");
        asm volatile("cp.async.wait_group 1;");
        __syncthreads();

        const uint32_t aBase = sb + (kt & 1) * BUF_B;
#pragma unroll
        for (int kk = 0; kk < 32; kk += 16) {
            const uint32_t kb = kk * 2;
            uint32_t ah[2][4], al[2][4], b[4][2];
            ldsm4(ah[0][0], ah[0][1], ah[0][2], ah[0][3], aBase + OFF_AH + aoff0 + kb);
            ldsm4(ah[1][0], ah[1][1], ah[1][2], ah[1][3], aBase + OFF_AH + aoff1 + kb);
            ldsm4(al[0][0], al[0][1], al[0][2], al[0][3], aBase + OFF_AL + aoff0 + kb);
            ldsm4(al[1][0], al[1][1], al[1][2], al[1][3], aBase + OFF_AL + aoff1 + kb);
            ldsm4(b[0][0], b[1][0], b[0][1], b[1][1],     aBase + OFF_B + boff0 + kb);
            ldsm4(b[2][0], b[3][0], b[2][1], b[3][1],     aBase + OFF_B + boff1 + kb);
#pragma unroll
            for (int mi = 0; mi < 2; mi++)
#pragma unroll
                for (int ni = 0; ni < 4; ni++) {
                    float* cc = c[mi][ni];
                    mma16816(cc[0], cc[1], cc[2], cc[3],
                             ah[mi][0], ah[mi][1], ah[mi][2], ah[mi][3],
                             b[ni][0], b[ni][1]);
                    mma16816(cc[0], cc[1], cc[2], cc[3],
                             al[mi][0], al[mi][1], al[mi][2], al[mi][3],
                             b[ni][0], b[ni][1]);
                }
        }
        __syncthreads();
    }

    // ---------------- epilogue ----------------
#pragma unroll
    for (int ni = 0; ni < 4; ni++) {
        const int col = colBase + warpN + ni * 8 + q * 2;
        const float bv0 = bias[col], bv1 = bias[col + 1];
#pragma unroll
        for (int mi = 0; mi < 2; mi++) {
            const int row0 = rowBase + warpM + mi * 16 + grp;
            float v00 = c[mi][ni][0] + bv0, v01 = c[mi][ni][1] + bv1;
            float v10 = c[mi][ni][2] + bv0, v11 = c[mi][ni][3] + bv1;
            if (ACT == 0) {
                v00 = fmaxf(v00, 0.f); v01 = fmaxf(v01, 0.f);
                v10 = fmaxf(v10, 0.f); v11 = fmaxf(v11, 0.f);
                __half h00 = __float2half_rn(v00), h01 = __float2half_rn(v01);
                __half h10 = __float2half_rn(v10), h11 = __float2half_rn(v11);
                __half2 H0 = __halves2half2(h00, h01);
                __half2 H1 = __halves2half2(h10, h11);
                __half2 L0 = __halves2half2(__float2half_rn(v00 - __half2float(h00)),
                                            __float2half_rn(v01 - __half2float(h01)));
                __half2 L1 = __halves2half2(__float2half_rn(v10 - __half2float(h10)),
                                            __float2half_rn(v11 - __half2float(h11)));
                *(uint32_t*)(Ch + (size_t)row0 * Mout + col) = *(uint32_t*)&H0;
                *(uint32_t*)(Ch + (size_t)(row0 + 8) * Mout + col) = *(uint32_t*)&H1;
                *(uint32_t*)(Cl + (size_t)row0 * Mout + col) = *(uint32_t*)&L0;
                *(uint32_t*)(Cl + (size_t)(row0 + 8) * Mout + col) = *(uint32_t*)&L1;
            } else {
                float2 o0 = make_float2(fast_tanh(v00), fast_tanh(v01));
                float2 o1 = make_float2(fast_tanh(v10), fast_tanh(v11));
                *(float2*)(Cf + (size_t)row0 * Mout + col) = o0;
                *(float2*)(Cf + (size_t)(row0 + 8) * Mout + col) = o1;
            }
        }
    }
}

// ---------------- weight round to fp16 ----------------
__global__ void wround(const float* __restrict__ s, __half* __restrict__ h, int n) {
    int idx = blockIdx.x * blockDim.x + threadIdx.x;
    if (idx >= n) return;
    h[idx] = __float2half_rn(s[idx]);
}
// W3: src row e*10+d -> dst row d*128+e
__global__ void wround_w3(const float* __restrict__ s, __half* __restrict__ h) {
    int idx = blockIdx.x * blockDim.x + threadIdx.x;
    if (idx >= M3 * H_F) return;
    int r = idx >> 9, k = idx & 511;
    int e = r / D_F, d = r - e * D_F;
    h[(size_t)(d * E_F + e) * H_F + k] = __float2half_rn(s[idx]);
}
__global__ void b3perm(const float* __restrict__ b3) {
    int idx = blockIdx.x * blockDim.x + threadIdx.x;
    if (idx >= M3) return;
    int e = idx / D_F, d = idx - e * D_F;
    g_b3p[d * E_F + e] = b3[idx];
}

// ---------------- spline ----------------
__global__ void spline_kernel(const float* __restrict__ t, const float* __restrict__ x) {
    int col = blockIdx.x * blockDim.x + threadIdx.x;
    if (col >= ND) return;
    int n = col / D_F, d = col % D_F;
    float tv[T_K];
#pragma unroll
    for (int i = 0; i < T_K; i++) tv[i] = t[i];
    float xv[T_K];
#pragma unroll
    for (int i = 0; i < T_K; i++) xv[i] = x[(n * T_K + i) * D_F + d];
    float h[T_K - 1];
#pragma unroll
    for (int i = 0; i < T_K - 1; i++) h[i] = tv[i + 1] - tv[i];
    float cp[T_K], dp[T_K];
    cp[0] = 0.f; dp[0] = 0.f;
#pragma unroll
    for (int i = 1; i < T_K - 1; i++) {
        float rhs = 6.f * ((xv[i + 1] - xv[i]) / h[i] - (xv[i] - xv[i - 1]) / h[i - 1]);
        float m = 2.f * (h[i - 1] + h[i]) - h[i - 1] * cp[i - 1];
        float inv = 1.f / m;
        cp[i] = h[i] * inv;
        dp[i] = (rhs - h[i - 1] * dp[i - 1]) * inv;
    }
    float Mv[T_K];
    Mv[T_K - 1] = 0.f;
#pragma unroll
    for (int i = T_K - 2; i >= 0; i--) Mv[i] = dp[i] - cp[i] * Mv[i + 1];
#pragma unroll
    for (int i = 0; i < T_K; i++) g_M[i * ND + col] = Mv[i];
}

// ---------------- dX/dt ----------------
__global__ void dx_kernel(const float* __restrict__ t, const float* __restrict__ x) {
    int idx = blockIdx.x * blockDim.x + threadIdx.x;
    if (idx >= NPTS * ND) return;
    int pt = idx / ND, col = idx - pt * ND;
    int n = col / D_F, d = col - n * D_F;
    int k = pt >> 2, j = pt & 3;
    float t0 = t[k], t1 = t[k + 1];
    float hs = t1 - t0;
    float s;
    if (j == 0) s = t0;
    else if (j == 1) s = t0 + hs / 3.0f;
    else if (j == 2) s = t0 + 2.0f * hs / 3.0f;
    else s = t1;
    int cnt = 0;
#pragma unroll
    for (int i = 0; i < T_K; i++) cnt += (t[i] <= s) ? 1 : 0;
    int i = min(max(cnt - 1, 0), T_K - 2);
    float hi = t[i + 1] - t[i];
    float xi  = x[(n * T_K + i) * D_F + d];
    float xi1 = x[(n * T_K + i + 1) * D_F + d];
    float Mi  = g_M[i * ND + col];
    float Mi1 = g_M[(i + 1) * ND + col];
    float u = s - t[i];
    float b = (xi1 - xi) / hi - hi * (2.0f * Mi + Mi1) / 6.0f;
    g_dX[idx] = b + Mi * u + (Mi1 - Mi) * (u * u) / (2.0f * hi);
}

// ---------------- z0 ----------------
__global__ void z0_kernel(const float* __restrict__ x, const float* __restrict__ We,
                          const float* __restrict__ be) {
    int idx = blockIdx.x * blockDim.x + threadIdx.x;
    if (idx >= NE) return;
    int n = idx / E_F, e = idx - n * E_F;
    float acc = be[e];
#pragma unroll
    for (int d = 0; d < D_F; d++) acc += x[n * T_K * D_F + d] * We[e * D_F + d];
    g_z[idx] = acc;
    __half h = __float2half_rn(acc);
    g_zh[idx] = h;
    g_zl[idx] = __float2half_rn(acc - __half2float(h));
}

// ---------------- fused einsum + RK combine (y3 layout [n][d*128+e]) ----------------
__global__ void vf_combine(const float* __restrict__ t, int k, int mode) {
    int idx = blockIdx.x * blockDim.x + threadIdx.x;
    if (idx >= NE) return;
    int n = idx >> 7, e = idx & 127;
    const float* y  = g_y3 + (size_t)n * M3 + e;
    const float* dx = g_dX + (size_t)(k * 4 + mode) * ND + n * D_F;
    float kv = 0.f;
#pragma unroll
    for (int d = 0; d < D_F; d++) kv += y[d * E_F] * dx[d];
    float hs = t[k + 1] - t[k];
    float z = g_z[idx];
    float zn;
    if (mode == 0)      { g_k1[idx] = kv; zn = z + hs * kv / 3.0f; }
    else if (mode == 1) { g_k2[idx] = kv; zn = z + hs * (kv - g_k1[idx] / 3.0f); }
    else if (mode == 2) { g_k3[idx] = kv; zn = z + hs * (g_k1[idx] - g_k2[idx] + kv); }
    else {
        zn = z + hs * (g_k1[idx] + 3.0f * (g_k2[idx] + g_k3[idx]) + kv) / 8.0f;
        g_z[idx] = zn;
    }
    __half h = __float2half_rn(zn);
    __half l = __float2half_rn(zn - __half2float(h));
    if (mode == 3) { g_zh[idx] = h;   g_zl[idx] = l; }
    else           { g_zinh[idx] = h; g_zinl[idx] = l; }
}

// ---------------- output with mask ----------------
__global__ void out_kernel(const int* __restrict__ mask, float* __restrict__ out) {
    int idx = blockIdx.x * blockDim.x + threadIdx.x;
    if (idx >= NE) return;
    int n = idx / E_F;
    out[idx] = (mask[n] != 0) ? g_z[idx] : 0.0f;
}

// ---------------- launcher ----------------
extern "C" void kernel_launch(void* const* d_in, const int* in_sizes, int n_in,
                              void* d_out, int out_size) {
    const float* t  = (const float*)d_in[0];
    const float* x  = (const float*)d_in[1];
    const int*   mask = (const int*)d_in[2];
    const float* We = (const float*)d_in[3];
    const float* be = (const float*)d_in[4];
    const float* W0 = (const float*)d_in[5];
    const float* b0 = (const float*)d_in[6];
    const float* W1 = (const float*)d_in[7];
    const float* b1 = (const float*)d_in[8];
    const float* W2 = (const float*)d_in[9];
    const float* b2 = (const float*)d_in[10];
    const float* W3 = (const float*)d_in[11];
    const float* b3 = (const float*)d_in[12];

    cudaFuncSetAttribute(mma_gemm<0>, cudaFuncAttributeMaxDynamicSharedMemorySize, SMEM_BYTES);
    cudaFuncSetAttribute(mma_gemm<1>, cudaFuncAttributeMaxDynamicSharedMemorySize, SMEM_BYTES);

    __half *zh, *zl, *zinh, *zinl, *y0h, *y0l, *y1h, *y1l, *y2h, *y2l;
    __half *W0r, *W1r, *W2r, *W3r;
    float *y3, *b3p;
    cudaGetSymbolAddress((void**)&zh, g_zh);     cudaGetSymbolAddress((void**)&zl, g_zl);
    cudaGetSymbolAddress((void**)&zinh, g_zinh); cudaGetSymbolAddress((void**)&zinl, g_zinl);
    cudaGetSymbolAddress((void**)&y0h, g_y0h);   cudaGetSymbolAddress((void**)&y0l, g_y0l);
    cudaGetSymbolAddress((void**)&y1h, g_y1h);   cudaGetSymbolAddress((void**)&y1l, g_y1l);
    cudaGetSymbolAddress((void**)&y2h, g_y2h);   cudaGetSymbolAddress((void**)&y2l, g_y2l);
    cudaGetSymbolAddress((void**)&W0r, g_W0);    cudaGetSymbolAddress((void**)&W1r, g_W1);
    cudaGetSymbolAddress((void**)&W2r, g_W2);    cudaGetSymbolAddress((void**)&W3r, g_W3);
    cudaGetSymbolAddress((void**)&y3, g_y3);
    cudaGetSymbolAddress((void**)&b3p, g_b3p);

    wround<<<(H_F * E_F + 255) / 256, 256>>>(W0, W0r, H_F * E_F);
    wround<<<(H_F * H_F + 255) / 256, 256>>>(W1, W1r, H_F * H_F);
    wround<<<(H_F * H_F + 255) / 256, 256>>>(W2, W2r, H_F * H_F);
    wround_w3<<<(M3 * H_F + 255) / 256, 256>>>(W3, W3r);
    b3perm<<<(M3 + 255) / 256, 256>>>(b3);

    spline_kernel<<<(ND + 255) / 256, 256>>>(t, x);
    dx_kernel<<<(NPTS * ND + 255) / 256, 256>>>(t, x);
    z0_kernel<<<(NE + 255) / 256, 256>>>(x, We, be);

    dim3 gH(H_F / 64, N_AG / 128);   // (8, 16)
    dim3 g3(M3 / 64, N_AG / 128);    // (20, 16)
    int eb = (NE + 255) / 256;

    for (int k = 0; k < T_K - 1; k++) {
        for (int stage = 0; stage < 4; stage++) {
            const __half* ah = (stage == 0) ? zh : zinh;
            const __half* al = (stage == 0) ? zl : zinl;
            mma_gemm<0><<<gH, 256, SMEM_BYTES>>>(ah,  al,  W0r, b0, y0h, y0l, nullptr, E_F, H_F);
            mma_gemm<0><<<gH, 256, SMEM_BYTES>>>(y0h, y0l, W1r, b1, y1h, y1l, nullptr, H_F, H_F);
            mma_gemm<0><<<gH, 256, SMEM_BYTES>>>(y1h, y1l, W2r, b2, y2h, y2l, nullptr, H_F, H_F);
            mma_gemm<1><<<g3, 256, SMEM_BYTES>>>(y2h, y2l, W3r, b3p, nullptr, nullptr, y3, H_F, M3);
            vf_combine<<<eb, 256>>>(t, k, stage);
        }
    }
    out_kernel<<<eb, 256>>>(mask, (float*)d_out);
}

// round 8
// speedup vs baseline: 2.1438x; 1.5912x over previous
#include <cuda_runtime.h>
#include <cuda_fp16.h>
#include <cstdint>

// ---------------- problem constants ----------------
#define N_AG 2048
#define T_K 16
#define D_F 10
#define E_F 128
#define H_F 512
#define M3 (E_F * D_F)      // 1280
#define ND (N_AG * D_F)
#define NPTS 60
#define NE (N_AG * E_F)

// ---------------- scratch ----------------
__device__ float g_M[T_K * ND];
__device__ float g_dX[NPTS * ND];
__device__ float g_z[NE];
__device__ float g_k1[NE];
__device__ float g_k2[NE];
__device__ float g_k3[NE];
__device__ float g_y3[N_AG * M3];     // layout [n][d*128+e]
__device__ float g_b3p[M3];

#define H16A __device__ __align__(16) __half
H16A g_zh[NE];
H16A g_zinh[NE];
H16A g_y0[N_AG * H_F];
H16A g_y1[N_AG * H_F];
H16A g_y2[N_AG * H_F];
H16A g_W0[H_F * E_F];
H16A g_W1[H_F * H_F];
H16A g_W2[H_F * H_F];
H16A g_W3[M3 * H_F];               // rows permuted: dst row = d*128+e

// ---------------- helpers ----------------
__device__ __forceinline__ uint32_t smem_u32(const void* p) {
    uint32_t a;
    asm("{ .reg .u64 t; cvta.to.shared.u64 t, %1; cvt.u32.u64 %0, t; }" : "=r"(a) : "l"(p));
    return a;
}
__device__ __forceinline__ void cp16(uint32_t s, const void* g) {
    asm volatile("cp.async.cg.shared.global [%0], [%1], 16;" :: "r"(s), "l"(g));
}
__device__ __forceinline__ void ldsm4(uint32_t& r0, uint32_t& r1, uint32_t& r2, uint32_t& r3,
                                      uint32_t a) {
    asm volatile("ldmatrix.sync.aligned.m8n8.x4.shared.b16 {%0,%1,%2,%3}, [%4];"
                 : "=r"(r0), "=r"(r1), "=r"(r2), "=r"(r3) : "r"(a));
}
__device__ __forceinline__ void mma16816(float& c0, float& c1, float& c2, float& c3,
                                         uint32_t a0, uint32_t a1, uint32_t a2, uint32_t a3,
                                         uint32_t b0, uint32_t b1) {
    asm volatile("mma.sync.aligned.m16n8k16.row.col.f32.f16.f16.f32 "
                 "{%0,%1,%2,%3},{%4,%5,%6,%7},{%8,%9},{%0,%1,%2,%3};"
                 : "+f"(c0), "+f"(c1), "+f"(c2), "+f"(c3)
                 : "r"(a0), "r"(a1), "r"(a2), "r"(a3), "r"(b0), "r"(b1));
}
__device__ __forceinline__ float fast_tanh(float x) {
    x = fminf(fmaxf(x, -15.f), 15.f);
    float e = __expf(-2.f * x);
    return (1.f - e) * __frcp_rn(1.f + e);
}

// smem per buffer: STRIDE 40 halves (80 B rows). A 10240 B, B 5120 B.
#define STRIDE 40
#define OFF_A  0
#define OFF_B  10240
#define BUF_B  15360
#define SMEM_BYTES (2 * BUF_B)      // 30720

// ---------------- fp16 HMMA GEMM: C = act(A @ W^T + bias) ----------------
// CTA 128x64, BK=32, 8 warps 4(M)x2(N), warp tile 32x32, ldmatrix feeds.
template <int ACT>  // 0: relu + fp16 out; 1: tanh + fp32 out
__global__ void __launch_bounds__(256) mma_gemm(
    const __half* __restrict__ A, const __half* __restrict__ Bw,
    const float* __restrict__ bias,
    __half* __restrict__ Ch, float* __restrict__ Cf, int K, int Mout)
{
    extern __shared__ char smem[];
    const uint32_t sb = smem_u32(smem);
    const int tid = threadIdx.x, wid = tid >> 5, lid = tid & 31;
    const int rowBase = blockIdx.y * 128;
    const int colBase = blockIdx.x * 64;
    const int warpM = (wid & 3) * 32;
    const int warpN = (wid >> 2) * 32;
    const int grp = lid >> 2, q = lid & 3;

    // cp.async mapping (BK=32)
    const int ar  = tid >> 1;            // A row 0..127
    const int acb = (tid & 1) * 16;      // half-offset
    const int br2 = tid >> 2;            // B row 0..63
    const int bcb = (tid & 3) * 8;

    const __half* gA = A  + (size_t)(rowBase + ar) * K + acb;
    const __half* gB = Bw + (size_t)(colBase + br2) * K + bcb;

    const uint32_t sA = sb + OFF_A + (ar * STRIDE + acb) * 2;
    const uint32_t sB = sb + OFF_B + (br2 * STRIDE + bcb) * 2;

    // ldmatrix lane addressing
    const int sel  = lid >> 3;
    const int lrow = (sel & 1) * 8 + (lid & 7);
    const int lcol = (sel >> 1) * 8;
    const uint32_t aoff0 = ((warpM + lrow) * STRIDE + lcol) * 2;
    const uint32_t aoff1 = ((warpM + 16 + lrow) * STRIDE + lcol) * 2;
    const uint32_t boff0 = ((warpN + lrow) * STRIDE + lcol) * 2;
    const uint32_t boff1 = ((warpN + 16 + lrow) * STRIDE + lcol) * 2;

    float c[2][4][4];
#pragma unroll
    for (int mi = 0; mi < 2; mi++)
#pragma unroll
        for (int ni = 0; ni < 4; ni++)
#pragma unroll
            for (int r = 0; r < 4; r++) c[mi][ni][r] = 0.f;

    const int NK = K >> 5;

    // prologue
    cp16(sA, gA); cp16(sA + 16, gA + 8);
    cp16(sB, gB);
    asm volatile("cp.async.commit_group;");

    for (int kt = 0; kt < NK; kt++) {
        if (kt + 1 < NK) {
            const int k0 = (kt + 1) << 5;
            const uint32_t bo = ((kt + 1) & 1) * BUF_B;
            cp16(sA + bo, gA + k0); cp16(sA + bo + 16, gA + k0 + 8);
            cp16(sB + bo, gB + k0);
        }
        asm volatile("cp.async.commit_group;");
        asm volatile("cp.async.wait_group 1;");
        __syncthreads();

        const uint32_t aBase = sb + (kt & 1) * BUF_B;
#pragma unroll
        for (int kk = 0; kk < 32; kk += 16) {
            const uint32_t kb = kk * 2;
            uint32_t a[2][4], b[4][2];
            ldsm4(a[0][0], a[0][1], a[0][2], a[0][3], aBase + OFF_A + aoff0 + kb);
            ldsm4(a[1][0], a[1][1], a[1][2], a[1][3], aBase + OFF_A + aoff1 + kb);
            ldsm4(b[0][0], b[1][0], b[0][1], b[1][1], aBase + OFF_B + boff0 + kb);
            ldsm4(b[2][0], b[3][0], b[2][1], b[3][1], aBase + OFF_B + boff1 + kb);
#pragma unroll
            for (int mi = 0; mi < 2; mi++)
#pragma unroll
                for (int ni = 0; ni < 4; ni++) {
                    float* cc = c[mi][ni];
                    mma16816(cc[0], cc[1], cc[2], cc[3],
                             a[mi][0], a[mi][1], a[mi][2], a[mi][3],
                             b[ni][0], b[ni][1]);
                }
        }
        __syncthreads();
    }

    // ---------------- epilogue ----------------
#pragma unroll
    for (int ni = 0; ni < 4; ni++) {
        const int col = colBase + warpN + ni * 8 + q * 2;
        const float bv0 = bias[col], bv1 = bias[col + 1];
#pragma unroll
        for (int mi = 0; mi < 2; mi++) {
            const int row0 = rowBase + warpM + mi * 16 + grp;
            float v00 = c[mi][ni][0] + bv0, v01 = c[mi][ni][1] + bv1;
            float v10 = c[mi][ni][2] + bv0, v11 = c[mi][ni][3] + bv1;
            if (ACT == 0) {
                v00 = fmaxf(v00, 0.f); v01 = fmaxf(v01, 0.f);
                v10 = fmaxf(v10, 0.f); v11 = fmaxf(v11, 0.f);
                __half2 H0 = __halves2half2(__float2half_rn(v00), __float2half_rn(v01));
                __half2 H1 = __halves2half2(__float2half_rn(v10), __float2half_rn(v11));
                *(uint32_t*)(Ch + (size_t)row0 * Mout + col) = *(uint32_t*)&H0;
                *(uint32_t*)(Ch + (size_t)(row0 + 8) * Mout + col) = *(uint32_t*)&H1;
            } else {
                float2 o0 = make_float2(fast_tanh(v00), fast_tanh(v01));
                float2 o1 = make_float2(fast_tanh(v10), fast_tanh(v11));
                *(float2*)(Cf + (size_t)row0 * Mout + col) = o0;
                *(float2*)(Cf + (size_t)(row0 + 8) * Mout + col) = o1;
            }
        }
    }
}

// ---------------- weight round to fp16 ----------------
__global__ void wround(const float* __restrict__ s, __half* __restrict__ h, int n) {
    int idx = blockIdx.x * blockDim.x + threadIdx.x;
    if (idx >= n) return;
    h[idx] = __float2half_rn(s[idx]);
}
// W3: src row e*10+d -> dst row d*128+e
__global__ void wround_w3(const float* __restrict__ s, __half* __restrict__ h) {
    int idx = blockIdx.x * blockDim.x + threadIdx.x;
    if (idx >= M3 * H_F) return;
    int r = idx >> 9, k = idx & 511;
    int e = r / D_F, d = r - e * D_F;
    h[(size_t)(d * E_F + e) * H_F + k] = __float2half_rn(s[idx]);
}
__global__ void b3perm(const float* __restrict__ b3) {
    int idx = blockIdx.x * blockDim.x + threadIdx.x;
    if (idx >= M3) return;
    int e = idx / D_F, d = idx - e * D_F;
    g_b3p[d * E_F + e] = b3[idx];
}

// ---------------- spline ----------------
__global__ void spline_kernel(const float* __restrict__ t, const float* __restrict__ x) {
    int col = blockIdx.x * blockDim.x + threadIdx.x;
    if (col >= ND) return;
    int n = col / D_F, d = col % D_F;
    float tv[T_K];
#pragma unroll
    for (int i = 0; i < T_K; i++) tv[i] = t[i];
    float xv[T_K];
#pragma unroll
    for (int i = 0; i < T_K; i++) xv[i] = x[(n * T_K + i) * D_F + d];
    float h[T_K - 1];
#pragma unroll
    for (int i = 0; i < T_K - 1; i++) h[i] = tv[i + 1] - tv[i];
    float cp[T_K], dp[T_K];
    cp[0] = 0.f; dp[0] = 0.f;
#pragma unroll
    for (int i = 1; i < T_K - 1; i++) {
        float rhs = 6.f * ((xv[i + 1] - xv[i]) / h[i] - (xv[i] - xv[i - 1]) / h[i - 1]);
        float m = 2.f * (h[i - 1] + h[i]) - h[i - 1] * cp[i - 1];
        float inv = 1.f / m;
        cp[i] = h[i] * inv;
        dp[i] = (rhs - h[i - 1] * dp[i - 1]) * inv;
    }
    float Mv[T_K];
    Mv[T_K - 1] = 0.f;
#pragma unroll
    for (int i = T_K - 2; i >= 0; i--) Mv[i] = dp[i] - cp[i] * Mv[i + 1];
#pragma unroll
    for (int i = 0; i < T_K; i++) g_M[i * ND + col] = Mv[i];
}

// ---------------- dX/dt ----------------
__global__ void dx_kernel(const float* __restrict__ t, const float* __restrict__ x) {
    int idx = blockIdx.x * blockDim.x + threadIdx.x;
    if (idx >= NPTS * ND) return;
    int pt = idx / ND, col = idx - pt * ND;
    int n = col / D_F, d = col - n * D_F;
    int k = pt >> 2, j = pt & 3;
    float t0 = t[k], t1 = t[k + 1];
    float hs = t1 - t0;
    float s;
    if (j == 0) s = t0;
    else if (j == 1) s = t0 + hs / 3.0f;
    else if (j == 2) s = t0 + 2.0f * hs / 3.0f;
    else s = t1;
    int cnt = 0;
#pragma unroll
    for (int i = 0; i < T_K; i++) cnt += (t[i] <= s) ? 1 : 0;
    int i = min(max(cnt - 1, 0), T_K - 2);
    float hi = t[i + 1] - t[i];
    float xi  = x[(n * T_K + i) * D_F + d];
    float xi1 = x[(n * T_K + i + 1) * D_F + d];
    float Mi  = g_M[i * ND + col];
    float Mi1 = g_M[(i + 1) * ND + col];
    float u = s - t[i];
    float b = (xi1 - xi) / hi - hi * (2.0f * Mi + Mi1) / 6.0f;
    g_dX[idx] = b + Mi * u + (Mi1 - Mi) * (u * u) / (2.0f * hi);
}

// ---------------- z0 ----------------
__global__ void z0_kernel(const float* __restrict__ x, const float* __restrict__ We,
                          const float* __restrict__ be) {
    int idx = blockIdx.x * blockDim.x + threadIdx.x;
    if (idx >= NE) return;
    int n = idx / E_F, e = idx - n * E_F;
    float acc = be[e];
#pragma unroll
    for (int d = 0; d < D_F; d++) acc += x[n * T_K * D_F + d] * We[e * D_F + d];
    g_z[idx] = acc;
    g_zh[idx] = __float2half_rn(acc);
}

// ---------------- fused einsum + RK combine (y3 layout [n][d*128+e]) ----------------
__global__ void vf_combine(const float* __restrict__ t, int k, int mode) {
    int idx = blockIdx.x * blockDim.x + threadIdx.x;
    if (idx >= NE) return;
    int n = idx >> 7, e = idx & 127;
    const float* y  = g_y3 + (size_t)n * M3 + e;
    const float* dx = g_dX + (size_t)(k * 4 + mode) * ND + n * D_F;
    float kv = 0.f;
#pragma unroll
    for (int d = 0; d < D_F; d++) kv += y[d * E_F] * dx[d];
    float hs = t[k + 1] - t[k];
    float z = g_z[idx];
    float zn;
    if (mode == 0)      { g_k1[idx] = kv; zn = z + hs * kv / 3.0f; }
    else if (mode == 1) { g_k2[idx] = kv; zn = z + hs * (kv - g_k1[idx] / 3.0f); }
    else if (mode == 2) { g_k3[idx] = kv; zn = z + hs * (g_k1[idx] - g_k2[idx] + kv); }
    else {
        zn = z + hs * (g_k1[idx] + 3.0f * (g_k2[idx] + g_k3[idx]) + kv) / 8.0f;
        g_z[idx] = zn;
    }
    if (mode == 3) g_zh[idx]   = __float2half_rn(zn);
    else           g_zinh[idx] = __float2half_rn(zn);
}

// ---------------- output with mask ----------------
__global__ void out_kernel(const int* __restrict__ mask, float* __restrict__ out) {
    int idx = blockIdx.x * blockDim.x + threadIdx.x;
    if (idx >= NE) return;
    int n = idx / E_F;
    out[idx] = (mask[n] != 0) ? g_z[idx] : 0.0f;
}

// ---------------- launcher ----------------
extern "C" void kernel_launch(void* const* d_in, const int* in_sizes, int n_in,
                              void* d_out, int out_size) {
    const float* t  = (const float*)d_in[0];
    const float* x  = (const float*)d_in[1];
    const int*   mask = (const int*)d_in[2];
    const float* We = (const float*)d_in[3];
    const float* be = (const float*)d_in[4];
    const float* W0 = (const float*)d_in[5];
    const float* b0 = (const float*)d_in[6];
    const float* W1 = (const float*)d_in[7];
    const float* b1 = (const float*)d_in[8];
    const float* W2 = (const float*)d_in[9];
    const float* b2 = (const float*)d_in[10];
    const float* W3 = (const float*)d_in[11];
    const float* b3 = (const float*)d_in[12];

    cudaFuncSetAttribute(mma_gemm<0>, cudaFuncAttributeMaxDynamicSharedMemorySize, SMEM_BYTES);
    cudaFuncSetAttribute(mma_gemm<1>, cudaFuncAttributeMaxDynamicSharedMemorySize, SMEM_BYTES);

    __half *zh, *zinh, *y0, *y1, *y2, *W0r, *W1r, *W2r, *W3r;
    float *y3, *b3p;
    cudaGetSymbolAddress((void**)&zh, g_zh);
    cudaGetSymbolAddress((void**)&zinh, g_zinh);
    cudaGetSymbolAddress((void**)&y0, g_y0);
    cudaGetSymbolAddress((void**)&y1, g_y1);
    cudaGetSymbolAddress((void**)&y2, g_y2);
    cudaGetSymbolAddress((void**)&W0r, g_W0);    cudaGetSymbolAddress((void**)&W1r, g_W1);
    cudaGetSymbolAddress((void**)&W2r, g_W2);    cudaGetSymbolAddress((void**)&W3r, g_W3);
    cudaGetSymbolAddress((void**)&y3, g_y3);
    cudaGetSymbolAddress((void**)&b3p, g_b3p);

    wround<<<(H_F * E_F + 255) / 256, 256>>>(W0, W0r, H_F * E_F);
    wround<<<(H_F * H_F + 255) / 256, 256>>>(W1, W1r, H_F * H_F);
    wround<<<(H_F * H_F + 255) / 256, 256>>>(W2, W2r, H_F * H_F);
    wround_w3<<<(M3 * H_F + 255) / 256, 256>>>(W3, W3r);
    b3perm<<<(M3 + 255) / 256, 256>>>(b3);

    spline_kernel<<<(ND + 255) / 256, 256>>>(t, x);
    dx_kernel<<<(NPTS * ND + 255) / 256, 256>>>(t, x);
    z0_kernel<<<(NE + 255) / 256, 256>>>(x, We, be);

    dim3 gH(H_F / 64, N_AG / 128);   // (8, 16)
    dim3 g3(M3 / 64, N_AG / 128);    // (20, 16)
    int eb = (NE + 255) / 256;

    for (int k = 0; k < T_K - 1; k++) {
        for (int stage = 0; stage < 4; stage++) {
            const __half* a0 = (stage == 0) ? zh : zinh;
            mma_gemm<0><<<gH, 256, SMEM_BYTES>>>(a0, W0r, b0, y0, nullptr, E_F, H_F);
            mma_gemm<0><<<gH, 256, SMEM_BYTES>>>(y0, W1r, b1, y1, nullptr, H_F, H_F);
            mma_gemm<0><<<gH, 256, SMEM_BYTES>>>(y1, W2r, b2, y2, nullptr, H_F, H_F);
            mma_gemm<1><<<g3, 256, SMEM_BYTES>>>(y2, W3r, b3p, nullptr, y3, H_F, M3);
            vf_combine<<<eb, 256>>>(t, k, stage);
        }
    }
    out_kernel<<<eb, 256>>>(mask, (float*)d_out);
}